// round 5
// baseline (speedup 1.0000x reference)
#include <cuda_runtime.h>
#include <cuda_bf16.h>

// Problem constants (fixed shapes for GAT_68762426409265)
#define NN  100000          // nodes
#define FIN 256             // input features
#define HID 64              // hidden
#define NC  40              // classes
#define EE  1600000         // edges (without self loops)
#define ET  (EE + NN)       // edges + self loops

// ---------------- device scratch (static, no allocation) ----------------
__device__ float g_h1[(size_t)NN * HID];     // layer1 projection
__device__ float g_out1[(size_t)NN * HID];   // layer1 aggregated (pre-relu)
__device__ float g_h2[(size_t)NN * NC];      // layer2 projection
__device__ float g_s1[NN];
__device__ float g_d1[NN];
__device__ float g_s2[NN];
__device__ float g_d2[NN];
__device__ int   g_cnt[NN];
__device__ int   g_scan[NN];
__device__ int   g_rowptr[NN + 1];
__device__ int   g_cursor[NN];
__device__ int   g_bsum[128];
__device__ int   g_boff[128];
__device__ int   g_srcs[ET];
__device__ float g_ews[ET];

// ---------------- CSR build ----------------
__global__ void zero_cnt_kernel() {
    int i = blockIdx.x * blockDim.x + threadIdx.x;
    if (i < NN) g_cnt[i] = 0;
}

__global__ void hist_kernel(const int* __restrict__ dst) {
    int e = blockIdx.x * blockDim.x + threadIdx.x;
    if (e >= ET) return;
    int d = (e < EE) ? dst[e] : (e - EE);
    atomicAdd(&g_cnt[d], 1);
}

__global__ void scan1_kernel() {
    __shared__ int tmp[1024];
    int t = threadIdx.x;
    int i = blockIdx.x * 1024 + t;
    tmp[t] = (i < NN) ? g_cnt[i] : 0;
    __syncthreads();
    #pragma unroll
    for (int off = 1; off < 1024; off <<= 1) {
        int x = 0;
        if (t >= off) x = tmp[t - off];
        __syncthreads();
        tmp[t] += x;
        __syncthreads();
    }
    if (i < NN) g_scan[i] = tmp[t];
    if (t == 1023) g_bsum[blockIdx.x] = tmp[1023];
}

__global__ void scan2_kernel(int nb) {
    __shared__ int tmp[128];
    int t = threadIdx.x;
    tmp[t] = (t < nb) ? g_bsum[t] : 0;
    __syncthreads();
    #pragma unroll
    for (int off = 1; off < 128; off <<= 1) {
        int x = 0;
        if (t >= off) x = tmp[t - off];
        __syncthreads();
        tmp[t] += x;
        __syncthreads();
    }
    g_boff[t] = (t == 0) ? 0 : tmp[t - 1];
}

__global__ void scan3_kernel() {
    int i = blockIdx.x * blockDim.x + threadIdx.x;
    if (i >= NN) return;
    g_rowptr[i + 1] = g_scan[i] + g_boff[i >> 10];
    if (i == 0) g_rowptr[0] = 0;
}

__global__ void cursor_kernel() {
    int i = blockIdx.x * blockDim.x + threadIdx.x;
    if (i < NN) g_cursor[i] = g_rowptr[i];
}

__global__ void fill_kernel(const int* __restrict__ src, const int* __restrict__ dst,
                            const float* __restrict__ ew) {
    int e = blockIdx.x * blockDim.x + threadIdx.x;
    if (e >= ET) return;
    int s, d;
    float w;
    if (e < EE) { s = src[e]; d = dst[e]; w = ew[e]; }
    else        { s = d = e - EE; w = 1.0f; }
    int pos = atomicAdd(&g_cursor[d], 1);
    g_srcs[pos] = s;
    g_ews[pos]  = w;
}

// ---------------- GEMM1: h1 = x @ W1, [NN,256]@[256,64] fp32 ----------------
__global__ __launch_bounds__(256) void gemm1_kernel(const float* __restrict__ X,
                                                    const float* __restrict__ W) {
    __shared__ float xs[64][36];   // pad 36: bank-spread + 16B-aligned rows
    __shared__ float ws[32][64];
    const int t  = threadIdx.x;
    const int tx = t & 15;
    const int ty = t >> 4;
    const int m0 = blockIdx.x * 64;

    float acc[4][4];
    #pragma unroll
    for (int i = 0; i < 4; i++)
        #pragma unroll
        for (int j = 0; j < 4; j++) acc[i][j] = 0.0f;

    for (int kc = 0; kc < FIN; kc += 32) {
        #pragma unroll
        for (int i = 0; i < 2; i++) {
            int idx = t + i * 256;
            int r = idx >> 3, c4 = (idx & 7) << 2;
            int gr = m0 + r;
            float4 v = make_float4(0.f, 0.f, 0.f, 0.f);
            if (gr < NN) v = *(const float4*)(X + (size_t)gr * FIN + kc + c4);
            *(float4*)&xs[r][c4] = v;
        }
        #pragma unroll
        for (int i = 0; i < 2; i++) {
            int idx = t + i * 256;
            int r = idx >> 4, c4 = (idx & 15) << 2;
            *(float4*)&ws[r][c4] = *(const float4*)(W + (size_t)(kc + r) * HID + c4);
        }
        __syncthreads();
        #pragma unroll
        for (int k = 0; k < 32; k++) {
            float4 b = *(float4*)&ws[k][tx * 4];
            #pragma unroll
            for (int i = 0; i < 4; i++) {
                float a = xs[ty * 4 + i][k];
                acc[i][0] = fmaf(a, b.x, acc[i][0]);
                acc[i][1] = fmaf(a, b.y, acc[i][1]);
                acc[i][2] = fmaf(a, b.z, acc[i][2]);
                acc[i][3] = fmaf(a, b.w, acc[i][3]);
            }
        }
        __syncthreads();
    }
    #pragma unroll
    for (int i = 0; i < 4; i++) {
        int row = m0 + ty * 4 + i;
        if (row < NN) {
            float4 v = make_float4(acc[i][0], acc[i][1], acc[i][2], acc[i][3]);
            *(float4*)(g_h1 + (size_t)row * HID + tx * 4) = v;
        }
    }
}

// ---------------- GEMM2: h2 = relu(out1) @ W2, [NN,64]@[64,40] fp32 ----------------
__global__ __launch_bounds__(320) void gemm2_kernel(const float* __restrict__ W2) {
    __shared__ float hs[64][65];
    __shared__ float ws[64][40];
    const int t  = threadIdx.x;              // 320 threads
    const int tx = t % 10;                   // 10 col groups (x4 = 40 cols)
    const int ty = t / 10;                   // 32 row groups (x2 = 64 rows)
    const int m0 = blockIdx.x * 64;

    for (int idx = t; idx < 64 * 64; idx += 320) {
        int r = idx >> 6, c = idx & 63;
        int gr = m0 + r;
        float v = 0.0f;
        if (gr < NN) v = g_out1[(size_t)gr * HID + c];
        hs[r][c] = v > 0.0f ? v : 0.0f;      // fused relu
    }
    for (int idx = t; idx < 64 * 40; idx += 320) {
        ws[idx / 40][idx % 40] = W2[idx];
    }
    __syncthreads();

    if (ty < 32) {
        float acc[2][4];
        #pragma unroll
        for (int i = 0; i < 2; i++)
            #pragma unroll
            for (int j = 0; j < 4; j++) acc[i][j] = 0.0f;
        #pragma unroll
        for (int k = 0; k < 64; k++) {
            float4 b = *(float4*)&ws[k][tx * 4];
            #pragma unroll
            for (int i = 0; i < 2; i++) {
                float a = hs[ty * 2 + i][k];
                acc[i][0] = fmaf(a, b.x, acc[i][0]);
                acc[i][1] = fmaf(a, b.y, acc[i][1]);
                acc[i][2] = fmaf(a, b.z, acc[i][2]);
                acc[i][3] = fmaf(a, b.w, acc[i][3]);
            }
        }
        #pragma unroll
        for (int i = 0; i < 2; i++) {
            int row = m0 + ty * 2 + i;
            if (row < NN) {
                float4 v = make_float4(acc[i][0], acc[i][1], acc[i][2], acc[i][3]);
                *(float4*)(g_h2 + (size_t)row * NC + tx * 4) = v;
            }
        }
    }
}

// ---------------- per-node attention scores s = h.a_src, d = h.a_dst ----------------
template <int D>
__global__ __launch_bounds__(256) void sd_kernel(const float* __restrict__ H,
                                                 const float* __restrict__ asrc,
                                                 const float* __restrict__ adst,
                                                 float* __restrict__ S,
                                                 float* __restrict__ Dd) {
    int w    = (blockIdx.x * blockDim.x + threadIdx.x) >> 5;
    int lane = threadIdx.x & 31;
    if (w >= NN) return;
    float ss = 0.0f, dd = 0.0f;
    for (int k = lane; k < D; k += 32) {
        float h = H[(size_t)w * D + k];
        ss = fmaf(h, asrc[k], ss);
        dd = fmaf(h, adst[k], dd);
    }
    #pragma unroll
    for (int off = 16; off; off >>= 1) {
        ss += __shfl_xor_sync(0xffffffffu, ss, off);
        dd += __shfl_xor_sync(0xffffffffu, dd, off);
    }
    if (lane == 0) { S[w] = ss; Dd[w] = dd; }
}

// ---------------- aggregation: warp per dst node, gather-style (no atomics) ---------
// alpha = exp(leaky(s[src]+d[v])) * ew / sum_e exp(leaky(...)); out[v] = sum alpha*H[src]
// Max-subtraction skipped: scores are O(few) (Gaussian-ish inputs), exp cannot overflow,
// and the softmax ratio is shift-invariant.
template <int D>
__global__ __launch_bounds__(256) void agg_kernel(const float* __restrict__ H,
                                                  const float* __restrict__ S,
                                                  const float* __restrict__ DA,
                                                  float* __restrict__ OUT) {
    int v    = (blockIdx.x * blockDim.x + threadIdx.x) >> 5;
    int lane = threadIdx.x & 31;
    if (v >= NN) return;
    int p0 = g_rowptr[v], p1 = g_rowptr[v + 1];
    float dv = DA[v];

    // denominator (lanes stride the edge list)
    float loc = 0.0f;
    for (int p = p0 + lane; p < p1; p += 32) {
        float sc = S[g_srcs[p]] + dv;
        sc = sc > 0.0f ? sc : 0.2f * sc;
        loc += __expf(sc);
    }
    #pragma unroll
    for (int off = 16; off; off >>= 1)
        loc += __shfl_xor_sync(0xffffffffu, loc, off);
    float inv = 1.0f / loc;   // >0 guaranteed: every node has a self loop

    // accumulate: lane covers 2 feature columns
    if (lane * 2 < D) {
        float2 acc = make_float2(0.0f, 0.0f);
        for (int p = p0; p < p1; p++) {
            int   sv = g_srcs[p];              // uniform across warp -> broadcast
            float sc = S[sv] + dv;
            sc = sc > 0.0f ? sc : 0.2f * sc;
            float alpha = __expf(sc) * g_ews[p] * inv;
            float2 hv = *(const float2*)(H + (size_t)sv * D + lane * 2);
            acc.x = fmaf(alpha, hv.x, acc.x);
            acc.y = fmaf(alpha, hv.y, acc.y);
        }
        *(float2*)(OUT + (size_t)v * D + lane * 2) = acc;
    }
}

// ---------------- launch ----------------
extern "C" void kernel_launch(void* const* d_in, const int* in_sizes, int n_in,
                              void* d_out, int out_size) {
    const float* x   = (const float*)d_in[0];
    const int*   ei  = (const int*)  d_in[1];
    const float* ew  = (const float*)d_in[2];
    const float* W1  = (const float*)d_in[3];
    const float* a1s = (const float*)d_in[4];
    const float* a1d = (const float*)d_in[5];
    const float* W2  = (const float*)d_in[6];
    const float* a2s = (const float*)d_in[7];
    const float* a2d = (const float*)d_in[8];
    float* out = (float*)d_out;

    const int* srcA = ei;
    const int* dstA = ei + EE;

    float *ph1, *pout1, *ph2, *ps1, *pd1, *ps2, *pd2;
    cudaGetSymbolAddress((void**)&ph1,   g_h1);
    cudaGetSymbolAddress((void**)&pout1, g_out1);
    cudaGetSymbolAddress((void**)&ph2,   g_h2);
    cudaGetSymbolAddress((void**)&ps1,   g_s1);
    cudaGetSymbolAddress((void**)&pd1,   g_d1);
    cudaGetSymbolAddress((void**)&ps2,   g_s2);
    cudaGetSymbolAddress((void**)&pd2,   g_d2);

    const int TPB = 256;
    // CSR build (shared by both layers)
    zero_cnt_kernel<<<(NN + TPB - 1) / TPB, TPB>>>();
    hist_kernel<<<(ET + TPB - 1) / TPB, TPB>>>(dstA);
    scan1_kernel<<<(NN + 1023) / 1024, 1024>>>();
    scan2_kernel<<<1, 128>>>((NN + 1023) / 1024);
    scan3_kernel<<<(NN + TPB - 1) / TPB, TPB>>>();
    cursor_kernel<<<(NN + TPB - 1) / TPB, TPB>>>();
    fill_kernel<<<(ET + TPB - 1) / TPB, TPB>>>(srcA, dstA, ew);

    // layer 1
    gemm1_kernel<<<(NN + 63) / 64, 256>>>(x, W1);
    sd_kernel<HID><<<(NN * 32 + TPB - 1) / TPB, TPB>>>(ph1, a1s, a1d, ps1, pd1);
    agg_kernel<HID><<<(NN * 32 + TPB - 1) / TPB, TPB>>>(ph1, ps1, pd1, pout1);

    // layer 2 (relu fused into gemm2 load)
    gemm2_kernel<<<(NN + 63) / 64, 320>>>(W2);
    sd_kernel<NC><<<(NN * 32 + TPB - 1) / TPB, TPB>>>(ph2, a2s, a2d, ps2, pd2);
    agg_kernel<NC><<<(NN * 32 + TPB - 1) / TPB, TPB>>>(ph2, ps2, pd2, out);
}

// round 7
// speedup vs baseline: 1.1638x; 1.1638x over previous
#include <cuda_runtime.h>
#include <cuda_bf16.h>

// Problem constants (fixed shapes for GAT_68762426409265)
#define NN  100000          // nodes
#define FIN 256             // input features
#define HID 64              // hidden
#define NC  40              // classes
#define EE  1600000         // edges (without self loops)
#define ET  (EE + NN)       // edges + self loops

// ---------------- device scratch (static, no allocation) ----------------
__device__ float g_h1[(size_t)NN * HID];     // layer1 projection
__device__ float g_out1[(size_t)NN * HID];   // layer1 aggregated (pre-relu)
__device__ float g_h2[(size_t)NN * NC];      // layer2 projection
__device__ float g_s1[NN];
__device__ float g_d1[NN];
__device__ float g_s2[NN];
__device__ float g_d2[NN];
__device__ int   g_cnt[NN];
__device__ int   g_scan[NN];
__device__ int   g_rowptr[NN + 1];
__device__ int   g_cursor[NN];
__device__ int   g_bsum[128];
__device__ int   g_boff[128];
__device__ int   g_srcs[ET];
__device__ float g_ews[ET];

// ---------------- small asm helpers ----------------
__device__ __forceinline__ unsigned f2tf(float x) {
    unsigned r; asm("cvt.rna.tf32.f32 %0, %1;" : "=r"(r) : "f"(x)); return r;
}
__device__ __forceinline__ void mma_tf32(float* c, const unsigned* a, const unsigned* b) {
    asm volatile("mma.sync.aligned.m16n8k8.row.col.f32.tf32.tf32.f32 "
                 "{%0,%1,%2,%3}, {%4,%5,%6,%7}, {%8,%9}, {%0,%1,%2,%3};"
                 : "+f"(c[0]), "+f"(c[1]), "+f"(c[2]), "+f"(c[3])
                 : "r"(a[0]), "r"(a[1]), "r"(a[2]), "r"(a[3]),
                   "r"(b[0]), "r"(b[1]));
}
__device__ __forceinline__ unsigned long long pk2(float x, float y) {
    unsigned long long r;
    asm("mov.b64 %0, {%1,%2};" : "=l"(r) : "f"(x), "f"(y));
    return r;
}
__device__ __forceinline__ float2 upk2(unsigned long long v) {
    float x, y;
    asm("mov.b64 {%0,%1}, %2;" : "=f"(x), "=f"(y) : "l"(v));
    return make_float2(x, y);
}
__device__ __forceinline__ unsigned long long ffma2(unsigned long long a,
                                                    unsigned long long b,
                                                    unsigned long long c) {
    unsigned long long d;
    asm("fma.rn.f32x2 %0, %1, %2, %3;" : "=l"(d) : "l"(a), "l"(b), "l"(c));
    return d;
}

// ---------------- CSR build ----------------
__global__ void zero_cnt_kernel() {
    int i = blockIdx.x * blockDim.x + threadIdx.x;
    if (i < NN) g_cnt[i] = 0;
}

__global__ void hist_kernel(const int* __restrict__ dst) {
    int e = blockIdx.x * blockDim.x + threadIdx.x;
    if (e >= ET) return;
    int d = (e < EE) ? dst[e] : (e - EE);
    atomicAdd(&g_cnt[d], 1);
}

__global__ void scan1_kernel() {
    __shared__ int tmp[1024];
    int t = threadIdx.x;
    int i = blockIdx.x * 1024 + t;
    tmp[t] = (i < NN) ? g_cnt[i] : 0;
    __syncthreads();
    #pragma unroll
    for (int off = 1; off < 1024; off <<= 1) {
        int x = 0;
        if (t >= off) x = tmp[t - off];
        __syncthreads();
        tmp[t] += x;
        __syncthreads();
    }
    if (i < NN) g_scan[i] = tmp[t];
    if (t == 1023) g_bsum[blockIdx.x] = tmp[1023];
}

__global__ void scan2_kernel(int nb) {
    __shared__ int tmp[128];
    int t = threadIdx.x;
    tmp[t] = (t < nb) ? g_bsum[t] : 0;
    __syncthreads();
    #pragma unroll
    for (int off = 1; off < 128; off <<= 1) {
        int x = 0;
        if (t >= off) x = tmp[t - off];
        __syncthreads();
        tmp[t] += x;
        __syncthreads();
    }
    g_boff[t] = (t == 0) ? 0 : tmp[t - 1];
}

__global__ void scan3_kernel() {
    int i = blockIdx.x * blockDim.x + threadIdx.x;
    if (i >= NN) return;
    g_rowptr[i + 1] = g_scan[i] + g_boff[i >> 10];
    if (i == 0) g_rowptr[0] = 0;
}

__global__ void cursor_kernel() {
    int i = blockIdx.x * blockDim.x + threadIdx.x;
    if (i < NN) g_cursor[i] = g_rowptr[i];
}

__global__ void fill_kernel(const int* __restrict__ src, const int* __restrict__ dst,
                            const float* __restrict__ ew) {
    int e = blockIdx.x * blockDim.x + threadIdx.x;
    if (e >= ET) return;
    int s, d;
    float w;
    if (e < EE) { s = src[e]; d = dst[e]; w = ew[e]; }
    else        { s = d = e - EE; w = 1.0f; }
    int pos = atomicAdd(&g_cursor[d], 1);
    g_srcs[pos] = s;
    g_ews[pos]  = w;
}

// ---------------- GEMM1: h1 = x @ W1, [NN,256]@[256,64] via 3xTF32 MMA ----------------
// BM=128, BK=16, BN=64. 8 warps: wm in 0..3 (32 rows each), wn in 0..1 (32 cols each).
// hi/lo decomposition recovers fp32 accuracy: ah*bh + ah*bl + al*bh.
__global__ __launch_bounds__(256) void gemm1_tc(const float* __restrict__ X,
                                                const float* __restrict__ W) {
    __shared__ unsigned Ah[128][20];   // pad 20: conflict-free frag loads
    __shared__ unsigned Al[128][20];
    __shared__ unsigned Bh[16][72];    // pad 72: k*8 + n covers all banks
    __shared__ unsigned Bl[16][72];

    const int t    = threadIdx.x;
    const int lane = t & 31;
    const int w    = t >> 5;
    const int wm   = w >> 1;          // 0..3
    const int wn   = w & 1;           // 0..1
    const int m0   = blockIdx.x * 128;

    float acc[2][4][4];
    #pragma unroll
    for (int i = 0; i < 2; i++)
        #pragma unroll
        for (int j = 0; j < 4; j++)
            #pragma unroll
            for (int k = 0; k < 4; k++) acc[i][j][k] = 0.0f;

    for (int kc = 0; kc < FIN; kc += 16) {
        // load A tile 128x16 (2 float4 per thread), hi/lo split
        #pragma unroll
        for (int i = 0; i < 2; i++) {
            int q  = t + i * 256;
            int r  = q >> 2;
            int c4 = (q & 3) << 2;
            int gr = m0 + r;
            float4 v = make_float4(0.f, 0.f, 0.f, 0.f);
            if (gr < NN) v = *(const float4*)(X + (size_t)gr * FIN + kc + c4);
            unsigned h0 = f2tf(v.x), h1 = f2tf(v.y), h2 = f2tf(v.z), h3 = f2tf(v.w);
            Ah[r][c4 + 0] = h0; Ah[r][c4 + 1] = h1;
            Ah[r][c4 + 2] = h2; Ah[r][c4 + 3] = h3;
            Al[r][c4 + 0] = f2tf(v.x - __uint_as_float(h0));
            Al[r][c4 + 1] = f2tf(v.y - __uint_as_float(h1));
            Al[r][c4 + 2] = f2tf(v.z - __uint_as_float(h2));
            Al[r][c4 + 3] = f2tf(v.w - __uint_as_float(h3));
        }
        // load B tile 16x64 (1 float4 per thread)
        {
            int r  = t >> 4;
            int c4 = (t & 15) << 2;
            float4 v = *(const float4*)(W + (size_t)(kc + r) * HID + c4);
            unsigned h0 = f2tf(v.x), h1 = f2tf(v.y), h2 = f2tf(v.z), h3 = f2tf(v.w);
            Bh[r][c4 + 0] = h0; Bh[r][c4 + 1] = h1;
            Bh[r][c4 + 2] = h2; Bh[r][c4 + 3] = h3;
            Bl[r][c4 + 0] = f2tf(v.x - __uint_as_float(h0));
            Bl[r][c4 + 1] = f2tf(v.y - __uint_as_float(h1));
            Bl[r][c4 + 2] = f2tf(v.z - __uint_as_float(h2));
            Bl[r][c4 + 3] = f2tf(v.w - __uint_as_float(h3));
        }
        __syncthreads();

        #pragma unroll
        for (int ks = 0; ks < 2; ks++) {
            unsigned bh[4][2], bl[4][2];
            #pragma unroll
            for (int nt = 0; nt < 4; nt++) {
                int n = wn * 32 + nt * 8 + (lane >> 2);
                int k = ks * 8 + (lane & 3);
                bh[nt][0] = Bh[k][n];     bh[nt][1] = Bh[k + 4][n];
                bl[nt][0] = Bl[k][n];     bl[nt][1] = Bl[k + 4][n];
            }
            #pragma unroll
            for (int mt = 0; mt < 2; mt++) {
                int r = wm * 32 + mt * 16 + (lane >> 2);
                int c = ks * 8 + (lane & 3);
                unsigned ah[4] = { Ah[r][c], Ah[r + 8][c], Ah[r][c + 4], Ah[r + 8][c + 4] };
                unsigned al[4] = { Al[r][c], Al[r + 8][c], Al[r][c + 4], Al[r + 8][c + 4] };
                #pragma unroll
                for (int nt = 0; nt < 4; nt++) {
                    mma_tf32(acc[mt][nt], ah, bh[nt]);
                    mma_tf32(acc[mt][nt], ah, bl[nt]);
                    mma_tf32(acc[mt][nt], al, bh[nt]);
                }
            }
        }
        __syncthreads();
    }

    // epilogue
    #pragma unroll
    for (int mt = 0; mt < 2; mt++) {
        int r0 = m0 + wm * 32 + mt * 16 + (lane >> 2);
        #pragma unroll
        for (int nt = 0; nt < 4; nt++) {
            int c0 = wn * 32 + nt * 8 + (lane & 3) * 2;
            if (r0 < NN)
                *(float2*)(g_h1 + (size_t)r0 * HID + c0) =
                    make_float2(acc[mt][nt][0], acc[mt][nt][1]);
            if (r0 + 8 < NN)
                *(float2*)(g_h1 + (size_t)(r0 + 8) * HID + c0) =
                    make_float2(acc[mt][nt][2], acc[mt][nt][3]);
        }
    }
}

// ---------------- GEMM2: h2 = relu(out1) @ W2, [NN,64]@[64,40] fp32 (f32x2 packed) ----
__global__ __launch_bounds__(320) void gemm2_kernel(const float* __restrict__ W2) {
    __shared__ float hs[64][65];
    __shared__ unsigned long long ws2[64][20];   // packed col pairs
    const int t  = threadIdx.x;              // 320 threads
    const int tx = t % 10;                   // 10 col groups (x4 = 40 cols)
    const int ty = t / 10;                   // 32 row groups (x2 = 64 rows)
    const int m0 = blockIdx.x * 64;

    for (int idx = t; idx < 64 * 64; idx += 320) {
        int r = idx >> 6, c = idx & 63;
        int gr = m0 + r;
        float v = 0.0f;
        if (gr < NN) v = g_out1[(size_t)gr * HID + c];
        hs[r][c] = v > 0.0f ? v : 0.0f;      // fused relu
    }
    for (int idx = t; idx < 64 * 20; idx += 320) {
        int r = idx / 20, j = idx % 20;
        float2 v = *(const float2*)(W2 + (size_t)r * NC + j * 2);
        ws2[r][j] = pk2(v.x, v.y);
    }
    __syncthreads();

    if (ty < 32) {
        unsigned long long acc[2][2] = {{0ull, 0ull}, {0ull, 0ull}};
        #pragma unroll
        for (int k = 0; k < 64; k++) {
            unsigned long long b0 = ws2[k][tx * 2];
            unsigned long long b1 = ws2[k][tx * 2 + 1];
            #pragma unroll
            for (int i = 0; i < 2; i++) {
                float a = hs[ty * 2 + i][k];
                unsigned long long aa = pk2(a, a);
                acc[i][0] = ffma2(aa, b0, acc[i][0]);
                acc[i][1] = ffma2(aa, b1, acc[i][1]);
            }
        }
        #pragma unroll
        for (int i = 0; i < 2; i++) {
            int row = m0 + ty * 2 + i;
            if (row < NN) {
                float2 lo = upk2(acc[i][0]);
                float2 hi = upk2(acc[i][1]);
                float4 v = make_float4(lo.x, lo.y, hi.x, hi.y);
                *(float4*)(g_h2 + (size_t)row * NC + tx * 4) = v;
            }
        }
    }
}

// ---------------- per-node attention scores s = h.a_src, d = h.a_dst ----------------
template <int D>
__global__ __launch_bounds__(256) void sd_kernel(const float* __restrict__ H,
                                                 const float* __restrict__ asrc,
                                                 const float* __restrict__ adst,
                                                 float* __restrict__ S,
                                                 float* __restrict__ Dd) {
    int w    = (blockIdx.x * blockDim.x + threadIdx.x) >> 5;
    int lane = threadIdx.x & 31;
    if (w >= NN) return;
    float ss = 0.0f, dd = 0.0f;
    for (int k = lane; k < D; k += 32) {
        float h = H[(size_t)w * D + k];
        ss = fmaf(h, asrc[k], ss);
        dd = fmaf(h, adst[k], dd);
    }
    #pragma unroll
    for (int off = 16; off; off >>= 1) {
        ss += __shfl_xor_sync(0xffffffffu, ss, off);
        dd += __shfl_xor_sync(0xffffffffu, dd, off);
    }
    if (lane == 0) { S[w] = ss; Dd[w] = dd; }
}

// ---------------- aggregation: warp per dst node, single fused pass ----------------
// out[v] = (sum_e exp(leaky(s_src+d_v)) * ew_e * H[src_e]) / (sum_e exp(leaky(...)))
// Normalization is linear -> accumulate numerator and denominator together, divide once.
// Each lane computes exp for ONE edge (1 expf + 1 random S read per edge total), then
// the warp broadcasts (w, src) via shuffle for the feature accumulation.
// Max-subtraction skipped: scores are O(few), exp cannot overflow, ratio shift-invariant.
template <int D>
__global__ __launch_bounds__(256) void agg_kernel(const float* __restrict__ H,
                                                  const float* __restrict__ S,
                                                  const float* __restrict__ DA,
                                                  float* __restrict__ OUT) {
    int v    = (blockIdx.x * blockDim.x + threadIdx.x) >> 5;
    int lane = threadIdx.x & 31;
    if (v >= NN) return;
    int p0 = g_rowptr[v], p1 = g_rowptr[v + 1];
    float dv = DA[v];

    int col = lane * 2;
    if (col > D - 2) col = D - 2;   // clamp (D=40: lanes 20..31 duplicate, don't store)

    float2 acc = make_float2(0.0f, 0.0f);
    float denom = 0.0f;

    for (int base = p0; base < p1; base += 32) {
        int p = base + lane;
        float wl = 0.0f;
        int   svl = 0;
        if (p < p1) {
            svl = g_srcs[p];
            float sc = S[svl] + dv;
            sc = sc > 0.0f ? sc : 0.2f * sc;
            float el = __expf(sc);
            denom += el;                     // denominator: exp only (no ew)
            wl = el * g_ews[p];              // numerator weight: exp * ew
        }
        int nj = p1 - base;
        if (nj > 32) nj = 32;
        for (int j = 0; j < nj; j++) {
            float wj = __shfl_sync(0xffffffffu, wl, j);
            int   sv = __shfl_sync(0xffffffffu, svl, j);
            float2 hv = *(const float2*)(H + (size_t)sv * D + col);
            acc.x = fmaf(wj, hv.x, acc.x);
            acc.y = fmaf(wj, hv.y, acc.y);
        }
    }
    #pragma unroll
    for (int off = 16; off; off >>= 1)
        denom += __shfl_xor_sync(0xffffffffu, denom, off);
    float inv = 1.0f / denom;   // >0 guaranteed: every node has a self loop

    if (lane * 2 < D)
        *(float2*)(OUT + (size_t)v * D + col) = make_float2(acc.x * inv, acc.y * inv);
}

// ---------------- launch ----------------
extern "C" void kernel_launch(void* const* d_in, const int* in_sizes, int n_in,
                              void* d_out, int out_size) {
    const float* x   = (const float*)d_in[0];
    const int*   ei  = (const int*)  d_in[1];
    const float* ew  = (const float*)d_in[2];
    const float* W1  = (const float*)d_in[3];
    const float* a1s = (const float*)d_in[4];
    const float* a1d = (const float*)d_in[5];
    const float* W2  = (const float*)d_in[6];
    const float* a2s = (const float*)d_in[7];
    const float* a2d = (const float*)d_in[8];
    float* out = (float*)d_out;

    const int* srcA = ei;
    const int* dstA = ei + EE;

    float *ph1, *pout1, *ph2, *ps1, *pd1, *ps2, *pd2;
    cudaGetSymbolAddress((void**)&ph1,   g_h1);
    cudaGetSymbolAddress((void**)&pout1, g_out1);
    cudaGetSymbolAddress((void**)&ph2,   g_h2);
    cudaGetSymbolAddress((void**)&ps1,   g_s1);
    cudaGetSymbolAddress((void**)&pd1,   g_d1);
    cudaGetSymbolAddress((void**)&ps2,   g_s2);
    cudaGetSymbolAddress((void**)&pd2,   g_d2);

    const int TPB = 256;
    // CSR build (shared by both layers)
    zero_cnt_kernel<<<(NN + TPB - 1) / TPB, TPB>>>();
    hist_kernel<<<(ET + TPB - 1) / TPB, TPB>>>(dstA);
    scan1_kernel<<<(NN + 1023) / 1024, 1024>>>();
    scan2_kernel<<<1, 128>>>((NN + 1023) / 1024);
    scan3_kernel<<<(NN + TPB - 1) / TPB, TPB>>>();
    cursor_kernel<<<(NN + TPB - 1) / TPB, TPB>>>();
    fill_kernel<<<(ET + TPB - 1) / TPB, TPB>>>(srcA, dstA, ew);

    // layer 1
    gemm1_tc<<<(NN + 127) / 128, 256>>>(x, W1);
    sd_kernel<HID><<<(NN * 32 + TPB - 1) / TPB, TPB>>>(ph1, a1s, a1d, ps1, pd1);
    agg_kernel<HID><<<(NN * 32 + TPB - 1) / TPB, TPB>>>(ph1, ps1, pd1, pout1);

    // layer 2 (relu fused into gemm2 load)
    gemm2_kernel<<<(NN + 63) / 64, 320>>>(W2);
    sd_kernel<NC><<<(NN * 32 + TPB - 1) / TPB, TPB>>>(ph2, a2s, a2d, ps2, pd2);
    agg_kernel<NC><<<(NN * 32 + TPB - 1) / TPB, TPB>>>(ph2, ps2, pd2, out);
}

// round 8
// speedup vs baseline: 1.4313x; 1.2298x over previous
#include <cuda_runtime.h>
#include <cuda_bf16.h>

// Problem constants (fixed shapes for GAT_68762426409265)
#define NN  100000          // nodes
#define FIN 256             // input features
#define HID 64              // hidden
#define NC  40              // classes
#define EE  1600000         // edges (without self loops)
#define ET  (EE + NN)       // edges + self loops

// ---------------- device scratch (static, no allocation) ----------------
__device__ float g_h1[(size_t)NN * HID];     // layer1 projection
__device__ float g_out1[(size_t)NN * HID];   // layer1 aggregated (pre-relu)
__device__ float g_h2[(size_t)NN * NC];      // layer2 projection
__device__ float g_s1[NN];
__device__ float g_d1[NN];
__device__ float g_s2[NN];
__device__ float g_d2[NN];
__device__ int   g_cnt[NN];
__device__ int   g_scan[NN];
__device__ int   g_rowptr[NN + 1];
__device__ int   g_cursor[NN];
__device__ int   g_bsum[128];
__device__ int   g_srcs[ET];
__device__ float g_ews[ET];

// ---------------- small asm helpers ----------------
__device__ __forceinline__ unsigned f2tf(float x) {
    unsigned r; asm("cvt.rna.tf32.f32 %0, %1;" : "=r"(r) : "f"(x)); return r;
}
__device__ __forceinline__ void mma_tf32(float* c, const unsigned* a, const unsigned* b) {
    asm volatile("mma.sync.aligned.m16n8k8.row.col.f32.tf32.tf32.f32 "
                 "{%0,%1,%2,%3}, {%4,%5,%6,%7}, {%8,%9}, {%0,%1,%2,%3};"
                 : "+f"(c[0]), "+f"(c[1]), "+f"(c[2]), "+f"(c[3])
                 : "r"(a[0]), "r"(a[1]), "r"(a[2]), "r"(a[3]),
                   "r"(b[0]), "r"(b[1]));
}
__device__ __forceinline__ unsigned long long pk2(float x, float y) {
    unsigned long long r;
    asm("mov.b64 %0, {%1,%2};" : "=l"(r) : "f"(x), "f"(y));
    return r;
}
__device__ __forceinline__ float2 upk2(unsigned long long v) {
    float x, y;
    asm("mov.b64 {%0,%1}, %2;" : "=f"(x), "=f"(y) : "l"(v));
    return make_float2(x, y);
}
__device__ __forceinline__ unsigned long long ffma2(unsigned long long a,
                                                    unsigned long long b,
                                                    unsigned long long c) {
    unsigned long long d;
    asm("fma.rn.f32x2 %0, %1, %2, %3;" : "=l"(d) : "l"(a), "l"(b), "l"(c));
    return d;
}

// ---------------- CSR build ----------------
__global__ void zero_cnt_kernel() {
    int i = blockIdx.x * blockDim.x + threadIdx.x;
    if (i < NN) g_cnt[i] = 0;
}

__global__ void hist_kernel(const int* __restrict__ dst) {
    int e = blockIdx.x * blockDim.x + threadIdx.x;
    if (e >= ET) return;
    int d = (e < EE) ? dst[e] : (e - EE);
    atomicAdd(&g_cnt[d], 1);
}

__global__ void scan1_kernel() {
    __shared__ int tmp[1024];
    int t = threadIdx.x;
    int i = blockIdx.x * 1024 + t;
    tmp[t] = (i < NN) ? g_cnt[i] : 0;
    __syncthreads();
    #pragma unroll
    for (int off = 1; off < 1024; off <<= 1) {
        int x = 0;
        if (t >= off) x = tmp[t - off];
        __syncthreads();
        tmp[t] += x;
        __syncthreads();
    }
    if (i < NN) g_scan[i] = tmp[t];
    if (t == 1023) g_bsum[blockIdx.x] = tmp[1023];
}

// Fused scan2 + scan3 + cursor: every block redundantly scans the 98 block sums
// (cheap), then produces rowptr (inclusive) and cursor (exclusive = inclusive - cnt).
__global__ void scan23_kernel(int nb) {
    __shared__ int bs[128];
    int t = threadIdx.x;
    if (t < 128) bs[t] = (t < nb) ? g_bsum[t] : 0;
    __syncthreads();
    #pragma unroll
    for (int off = 1; off < 128; off <<= 1) {
        int x = 0;
        if (t < 128 && t >= off) x = bs[t - off];
        __syncthreads();
        if (t < 128) bs[t] += x;
        __syncthreads();
    }
    int i = blockIdx.x * 1024 + t;
    if (i < NN) {
        int blk  = i >> 10;
        int boff = blk ? bs[blk - 1] : 0;
        int inc  = g_scan[i] + boff;
        g_rowptr[i + 1] = inc;
        g_cursor[i]     = inc - g_cnt[i];
        if (i == 0) g_rowptr[0] = 0;
    }
}

__global__ void fill_kernel(const int* __restrict__ src, const int* __restrict__ dst,
                            const float* __restrict__ ew) {
    int e = blockIdx.x * blockDim.x + threadIdx.x;
    if (e >= ET) return;
    int s, d;
    float w;
    if (e < EE) { s = src[e]; d = dst[e]; w = ew[e]; }
    else        { s = d = e - EE; w = 1.0f; }
    int pos = atomicAdd(&g_cursor[d], 1);
    g_srcs[pos] = s;
    g_ews[pos]  = w;
}

// ---------------- GEMM1: h1 = x @ W1, [NN,256]@[256,64] via 3xTF32 MMA --------------
// BM=128, BK=16, BN=64. 8 warps: wm 0..3 (32 rows each), wn 0..1 (32 cols each).
// hi/lo decomposition recovers fp32 accuracy: ah*bh + ah*bl + al*bh.
// Fused epilogue: s1 = h1 . a1s, d1 = h1 . a1d (quad-shuffle + smem cross-warp reduce).
__global__ __launch_bounds__(256) void gemm1_tc(const float* __restrict__ X,
                                                const float* __restrict__ W,
                                                const float* __restrict__ A1S,
                                                const float* __restrict__ A1D) {
    __shared__ unsigned Ah[128][20];   // pad 20: conflict-free frag loads
    __shared__ unsigned Al[128][20];
    __shared__ unsigned Bh[16][72];    // pad 72: k*8 + n covers all banks
    __shared__ unsigned Bl[16][72];
    __shared__ float    s_sm[2][128];
    __shared__ float    d_sm[2][128];

    const int t    = threadIdx.x;
    const int lane = t & 31;
    const int w    = t >> 5;
    const int wm   = w >> 1;          // 0..3
    const int wn   = w & 1;           // 0..1
    const int m0   = blockIdx.x * 128;

    float acc[2][4][4];
    #pragma unroll
    for (int i = 0; i < 2; i++)
        #pragma unroll
        for (int j = 0; j < 4; j++)
            #pragma unroll
            for (int k = 0; k < 4; k++) acc[i][j][k] = 0.0f;

    for (int kc = 0; kc < FIN; kc += 16) {
        // load A tile 128x16 (2 float4 per thread), hi/lo split
        #pragma unroll
        for (int i = 0; i < 2; i++) {
            int q  = t + i * 256;
            int r  = q >> 2;
            int c4 = (q & 3) << 2;
            int gr = m0 + r;
            float4 v = make_float4(0.f, 0.f, 0.f, 0.f);
            if (gr < NN) v = *(const float4*)(X + (size_t)gr * FIN + kc + c4);
            unsigned h0 = f2tf(v.x), h1 = f2tf(v.y), h2 = f2tf(v.z), h3 = f2tf(v.w);
            Ah[r][c4 + 0] = h0; Ah[r][c4 + 1] = h1;
            Ah[r][c4 + 2] = h2; Ah[r][c4 + 3] = h3;
            Al[r][c4 + 0] = f2tf(v.x - __uint_as_float(h0));
            Al[r][c4 + 1] = f2tf(v.y - __uint_as_float(h1));
            Al[r][c4 + 2] = f2tf(v.z - __uint_as_float(h2));
            Al[r][c4 + 3] = f2tf(v.w - __uint_as_float(h3));
        }
        // load B tile 16x64 (1 float4 per thread)
        {
            int r  = t >> 4;
            int c4 = (t & 15) << 2;
            float4 v = *(const float4*)(W + (size_t)(kc + r) * HID + c4);
            unsigned h0 = f2tf(v.x), h1 = f2tf(v.y), h2 = f2tf(v.z), h3 = f2tf(v.w);
            Bh[r][c4 + 0] = h0; Bh[r][c4 + 1] = h1;
            Bh[r][c4 + 2] = h2; Bh[r][c4 + 3] = h3;
            Bl[r][c4 + 0] = f2tf(v.x - __uint_as_float(h0));
            Bl[r][c4 + 1] = f2tf(v.y - __uint_as_float(h1));
            Bl[r][c4 + 2] = f2tf(v.z - __uint_as_float(h2));
            Bl[r][c4 + 3] = f2tf(v.w - __uint_as_float(h3));
        }
        __syncthreads();

        #pragma unroll
        for (int ks = 0; ks < 2; ks++) {
            unsigned bh[4][2], bl[4][2];
            #pragma unroll
            for (int nt = 0; nt < 4; nt++) {
                int n = wn * 32 + nt * 8 + (lane >> 2);
                int k = ks * 8 + (lane & 3);
                bh[nt][0] = Bh[k][n];     bh[nt][1] = Bh[k + 4][n];
                bl[nt][0] = Bl[k][n];     bl[nt][1] = Bl[k + 4][n];
            }
            #pragma unroll
            for (int mt = 0; mt < 2; mt++) {
                int r = wm * 32 + mt * 16 + (lane >> 2);
                int c = ks * 8 + (lane & 3);
                unsigned ah[4] = { Ah[r][c], Ah[r + 8][c], Ah[r][c + 4], Ah[r + 8][c + 4] };
                unsigned al[4] = { Al[r][c], Al[r + 8][c], Al[r][c + 4], Al[r + 8][c + 4] };
                #pragma unroll
                for (int nt = 0; nt < 4; nt++) {
                    mma_tf32(acc[mt][nt], ah, bh[nt]);
                    mma_tf32(acc[mt][nt], ah, bl[nt]);
                    mma_tf32(acc[mt][nt], al, bh[nt]);
                }
            }
        }
        __syncthreads();
    }

    // epilogue: store h1 + fused s/d dot products
    float a_s[8], a_d[8];
    #pragma unroll
    for (int nt = 0; nt < 4; nt++) {
        int c0 = wn * 32 + nt * 8 + (lane & 3) * 2;
        a_s[nt * 2]     = A1S[c0];
        a_s[nt * 2 + 1] = A1S[c0 + 1];
        a_d[nt * 2]     = A1D[c0];
        a_d[nt * 2 + 1] = A1D[c0 + 1];
    }

    #pragma unroll
    for (int mt = 0; mt < 2; mt++) {
        int r0 = m0 + wm * 32 + mt * 16 + (lane >> 2);
        float sp0 = 0.f, dp0 = 0.f, sp1 = 0.f, dp1 = 0.f;
        #pragma unroll
        for (int nt = 0; nt < 4; nt++) {
            int c0 = wn * 32 + nt * 8 + (lane & 3) * 2;
            if (r0 < NN)
                *(float2*)(g_h1 + (size_t)r0 * HID + c0) =
                    make_float2(acc[mt][nt][0], acc[mt][nt][1]);
            if (r0 + 8 < NN)
                *(float2*)(g_h1 + (size_t)(r0 + 8) * HID + c0) =
                    make_float2(acc[mt][nt][2], acc[mt][nt][3]);
            sp0 = fmaf(acc[mt][nt][0], a_s[nt * 2],     sp0);
            sp0 = fmaf(acc[mt][nt][1], a_s[nt * 2 + 1], sp0);
            sp1 = fmaf(acc[mt][nt][2], a_s[nt * 2],     sp1);
            sp1 = fmaf(acc[mt][nt][3], a_s[nt * 2 + 1], sp1);
            dp0 = fmaf(acc[mt][nt][0], a_d[nt * 2],     dp0);
            dp0 = fmaf(acc[mt][nt][1], a_d[nt * 2 + 1], dp0);
            dp1 = fmaf(acc[mt][nt][2], a_d[nt * 2],     dp1);
            dp1 = fmaf(acc[mt][nt][3], a_d[nt * 2 + 1], dp1);
        }
        // reduce over the quad (lane&3)
        #pragma unroll
        for (int off = 1; off < 4; off <<= 1) {
            sp0 += __shfl_xor_sync(0xffffffffu, sp0, off);
            sp1 += __shfl_xor_sync(0xffffffffu, sp1, off);
            dp0 += __shfl_xor_sync(0xffffffffu, dp0, off);
            dp1 += __shfl_xor_sync(0xffffffffu, dp1, off);
        }
        if ((lane & 3) == 0) {
            int lr = wm * 32 + mt * 16 + (lane >> 2);
            s_sm[wn][lr]     = sp0;
            s_sm[wn][lr + 8] = sp1;
            d_sm[wn][lr]     = dp0;
            d_sm[wn][lr + 8] = dp1;
        }
    }
    __syncthreads();
    if (t < 128) {
        int gr = m0 + t;
        if (gr < NN) {
            g_s1[gr] = s_sm[0][t] + s_sm[1][t];
            g_d1[gr] = d_sm[0][t] + d_sm[1][t];
        }
    }
}

// ---------------- GEMM2: h2 = relu(out1) @ W2, [NN,64]@[64,40] fp32 (f32x2) ----------
// Fused epilogue: s2 = h2 . a2s, d2 = h2 . a2d via smem partials (deterministic).
__global__ __launch_bounds__(320) void gemm2_kernel(const float* __restrict__ W2,
                                                    const float* __restrict__ A2S,
                                                    const float* __restrict__ A2D) {
    __shared__ float hs[64][65];
    __shared__ unsigned long long ws2[64][20];   // packed col pairs
    __shared__ float s_sm2[10][64];
    __shared__ float d_sm2[10][64];
    const int t  = threadIdx.x;              // 320 threads
    const int tx = t % 10;                   // 10 col groups (x4 = 40 cols)
    const int ty = t / 10;                   // 32 row groups (x2 = 64 rows)
    const int m0 = blockIdx.x * 64;

    for (int idx = t; idx < 64 * 64; idx += 320) {
        int r = idx >> 6, c = idx & 63;
        int gr = m0 + r;
        float v = 0.0f;
        if (gr < NN) v = g_out1[(size_t)gr * HID + c];
        hs[r][c] = v > 0.0f ? v : 0.0f;      // fused relu
    }
    for (int idx = t; idx < 64 * 20; idx += 320) {
        int r = idx / 20, j = idx % 20;
        float2 v = *(const float2*)(W2 + (size_t)r * NC + j * 2);
        ws2[r][j] = pk2(v.x, v.y);
    }
    __syncthreads();

    if (ty < 32) {
        unsigned long long acc[2][2] = {{0ull, 0ull}, {0ull, 0ull}};
        #pragma unroll
        for (int k = 0; k < 64; k++) {
            unsigned long long b0 = ws2[k][tx * 2];
            unsigned long long b1 = ws2[k][tx * 2 + 1];
            #pragma unroll
            for (int i = 0; i < 2; i++) {
                float a = hs[ty * 2 + i][k];
                unsigned long long aa = pk2(a, a);
                acc[i][0] = ffma2(aa, b0, acc[i][0]);
                acc[i][1] = ffma2(aa, b1, acc[i][1]);
            }
        }
        float as0 = A2S[tx * 4], as1 = A2S[tx * 4 + 1], as2 = A2S[tx * 4 + 2], as3 = A2S[tx * 4 + 3];
        float ad0 = A2D[tx * 4], ad1 = A2D[tx * 4 + 1], ad2 = A2D[tx * 4 + 2], ad3 = A2D[tx * 4 + 3];
        #pragma unroll
        for (int i = 0; i < 2; i++) {
            int row = m0 + ty * 2 + i;
            float2 lo = upk2(acc[i][0]);
            float2 hi = upk2(acc[i][1]);
            if (row < NN) {
                float4 v = make_float4(lo.x, lo.y, hi.x, hi.y);
                *(float4*)(g_h2 + (size_t)row * NC + tx * 4) = v;
            }
            float sp = lo.x * as0 + lo.y * as1 + hi.x * as2 + hi.y * as3;
            float dp = lo.x * ad0 + lo.y * ad1 + hi.x * ad2 + hi.y * ad3;
            s_sm2[tx][ty * 2 + i] = sp;
            d_sm2[tx][ty * 2 + i] = dp;
        }
    }
    __syncthreads();
    if (t < 64) {
        int gr = m0 + t;
        if (gr < NN) {
            float ss = 0.f, dd = 0.f;
            #pragma unroll
            for (int j = 0; j < 10; j++) { ss += s_sm2[j][t]; dd += d_sm2[j][t]; }
            g_s2[gr] = ss;
            g_d2[gr] = dd;
        }
    }
}

// ---------------- aggregation: warp per dst node, single fused pass ----------------
// out[v] = (sum_e exp(leaky(s_src+d_v)) * ew_e * H[src_e]) / (sum_e exp(leaky(...)))
// Each lane computes exp for ONE edge, then the warp broadcasts (w, src) via shuffle
// for the feature accumulation. Max-subtraction skipped (scores O(few), shift-invariant).
template <int D>
__global__ __launch_bounds__(256) void agg_kernel(const float* __restrict__ H,
                                                  const float* __restrict__ S,
                                                  const float* __restrict__ DA,
                                                  float* __restrict__ OUT) {
    int v    = (blockIdx.x * blockDim.x + threadIdx.x) >> 5;
    int lane = threadIdx.x & 31;
    if (v >= NN) return;
    int p0 = g_rowptr[v], p1 = g_rowptr[v + 1];
    float dv = DA[v];

    int col = lane * 2;
    if (col > D - 2) col = D - 2;   // clamp (D=40: lanes 20..31 duplicate, don't store)

    float2 acc = make_float2(0.0f, 0.0f);
    float denom = 0.0f;

    for (int base = p0; base < p1; base += 32) {
        int p = base + lane;
        float wl = 0.0f;
        int   svl = 0;
        if (p < p1) {
            svl = g_srcs[p];
            float sc = S[svl] + dv;
            sc = sc > 0.0f ? sc : 0.2f * sc;
            float el = __expf(sc);
            denom += el;                     // denominator: exp only (no ew)
            wl = el * g_ews[p];              // numerator weight: exp * ew
        }
        int nj = p1 - base;
        if (nj > 32) nj = 32;
        for (int j = 0; j < nj; j++) {
            float wj = __shfl_sync(0xffffffffu, wl, j);
            int   sv = __shfl_sync(0xffffffffu, svl, j);
            float2 hv = *(const float2*)(H + (size_t)sv * D + col);
            acc.x = fmaf(wj, hv.x, acc.x);
            acc.y = fmaf(wj, hv.y, acc.y);
        }
    }
    #pragma unroll
    for (int off = 16; off; off >>= 1)
        denom += __shfl_xor_sync(0xffffffffu, denom, off);
    float inv = 1.0f / denom;   // >0 guaranteed: every node has a self loop

    if (lane * 2 < D)
        *(float2*)(OUT + (size_t)v * D + col) = make_float2(acc.x * inv, acc.y * inv);
}

// ---------------- launch ----------------
extern "C" void kernel_launch(void* const* d_in, const int* in_sizes, int n_in,
                              void* d_out, int out_size) {
    const float* x   = (const float*)d_in[0];
    const int*   ei  = (const int*)  d_in[1];
    const float* ew  = (const float*)d_in[2];
    const float* W1  = (const float*)d_in[3];
    const float* a1s = (const float*)d_in[4];
    const float* a1d = (const float*)d_in[5];
    const float* W2  = (const float*)d_in[6];
    const float* a2s = (const float*)d_in[7];
    const float* a2d = (const float*)d_in[8];
    float* out = (float*)d_out;

    const int* srcA = ei;
    const int* dstA = ei + EE;

    float *ph1, *pout1, *ph2, *ps1, *pd1, *ps2, *pd2;
    cudaGetSymbolAddress((void**)&ph1,   g_h1);
    cudaGetSymbolAddress((void**)&pout1, g_out1);
    cudaGetSymbolAddress((void**)&ph2,   g_h2);
    cudaGetSymbolAddress((void**)&ps1,   g_s1);
    cudaGetSymbolAddress((void**)&pd1,   g_d1);
    cudaGetSymbolAddress((void**)&ps2,   g_s2);
    cudaGetSymbolAddress((void**)&pd2,   g_d2);

    // Capture-safe side stream + fork/join events (created once; work identical per call)
    static cudaStream_t s2 = nullptr;
    static cudaEvent_t  evF = nullptr, evJ = nullptr;
    if (!s2) {
        cudaStreamCreateWithFlags(&s2, cudaStreamNonBlocking);
        cudaEventCreateWithFlags(&evF, cudaEventDisableTiming);
        cudaEventCreateWithFlags(&evJ, cudaEventDisableTiming);
    }

    const int TPB = 256;
    const int nb  = (NN + 1023) / 1024;

    // Fork: CSR build on side stream, concurrent with gemm1 on the main stream
    cudaEventRecord(evF, 0);
    cudaStreamWaitEvent(s2, evF, 0);
    zero_cnt_kernel<<<(NN + TPB - 1) / TPB, TPB, 0, s2>>>();
    hist_kernel<<<(ET + TPB - 1) / TPB, TPB, 0, s2>>>(dstA);
    scan1_kernel<<<nb, 1024, 0, s2>>>();
    scan23_kernel<<<nb, 1024, 0, s2>>>(nb);
    fill_kernel<<<(ET + TPB - 1) / TPB, TPB, 0, s2>>>(srcA, dstA, ew);
    cudaEventRecord(evJ, s2);

    // Main stream: layer-1 projection (+ fused s1/d1) runs during CSR build
    gemm1_tc<<<(NN + 127) / 128, 256>>>(x, W1, a1s, a1d);

    // Join, then the serial tail
    cudaStreamWaitEvent(0, evJ, 0);
    agg_kernel<HID><<<(NN * 32 + TPB - 1) / TPB, TPB>>>(ph1, ps1, pd1, pout1);
    gemm2_kernel<<<(NN + 63) / 64, 320>>>(W2, a2s, a2d);
    agg_kernel<NC><<<(NN * 32 + TPB - 1) / TPB, TPB>>>(ph2, ps2, pd2, out);
}